// round 3
// baseline (speedup 1.0000x reference)
#include <cuda_runtime.h>
#include <math.h>

#define NN     50000
#define RR     4
#define DD     5
#define BB     8
#define TT     10
#define E_RECN 1500000
#define E_INN  200000
#define N_INN  17400
#define RNN    (RR * NN)   // 200000
#define ZLEN   (DD * NN)   // 250000
#define IN_QUADS  (E_INN / 4)              // 50000

#define SCAN_CH   1024
#define SCAN_NBLK ((ZLEN + SCAN_CH - 1) / SCAN_CH)   // 245

// ------------------------- device scratch (no allocs) -------------------------
__device__ float4        g_total[BB * NN];
__device__ float         g_v[BB * NN];
__device__ float         g_r[BB * NN];
__device__ float         g_a1[BB * NN];
__device__ float         g_a2[BB * NN];
__device__ float4        g_psc_rise[BB * NN];
__device__ float4        g_psc[BB * NN];
__device__ unsigned char g_zmask[ZLEN];
__device__ unsigned char g_xmask[TT * N_INN];
__device__ float2        g_ascd[NN];

// CSR sort scratch
__device__ int  g_zidx[E_RECN];
__device__ int  g_cnt[ZLEN];
__device__ int  g_part[SCAN_NBLK + 1];
__device__ int  g_rowptr[ZLEN + 1];
__device__ int  g_fill[ZLEN];
__device__ int2 g_edges[E_RECN];      // (tgt, w as int) sorted by zidx

// frontier ping-pong
__device__ int  g_fcount[2];
__device__ int  g_flist[2][ZLEN];

// ------------------------------- init kernel ---------------------------------
__global__ void init_kernel(const float* __restrict__ x,
                            const float* __restrict__ bkg_w,
                            const float2* __restrict__ param_k,
                            const float* __restrict__ v0)
{
    int i      = blockIdx.x * blockDim.x + threadIdx.x;
    int stride = gridDim.x * blockDim.x;

    if (i == 0) { g_fcount[0] = 0; g_fcount[1] = 0; }

    const float4* bkg4 = reinterpret_cast<const float4*>(bkg_w);
    for (int j = i; j < BB * NN; j += stride) {
        g_total[j] = bkg4[j % NN];
        g_v[j]  = v0[j];
        g_r[j]  = 0.0f;
        g_a1[j] = 0.0f;
        g_a2[j] = 0.0f;
        g_psc_rise[j] = make_float4(0.f, 0.f, 0.f, 0.f);
        g_psc[j]      = make_float4(0.f, 0.f, 0.f, 0.f);
    }
    for (int j = i; j < ZLEN; j += stride) { g_zmask[j] = 0; g_cnt[j] = 0; }
    for (int j = i; j < TT * N_INN; j += stride) {
        int t = j / N_INN;
        int s = j - t * N_INN;
        unsigned m = 0;
        #pragma unroll
        for (int b = 0; b < BB; b++) {
            if (x[(t * BB + b) * N_INN + s] > 0.5f) m |= (1u << b);
        }
        g_xmask[j] = (unsigned char)m;
    }
    for (int j = i; j < NN; j += stride) {
        float2 pk = param_k[j];
        float s0 = 1.0f / (1.0f + expf(-pk.x));
        float s1 = 1.0f / (1.0f + expf(-pk.y));
        g_ascd[j] = make_float2(expf(-s0), expf(-s1));
    }
}

// ------------------------- CSR build (counting sort) --------------------------
__global__ void hist_kernel(const int* __restrict__ rec_src)
{
    int i      = blockIdx.x * blockDim.x + threadIdx.x;
    int stride = gridDim.x * blockDim.x;
    for (int e = i; e < E_RECN; e += stride) {
        int src = rec_src[e];
        int d = src / NN;
        int n = src - d * NN;
        int j = d * NN + n;
        g_zidx[e] = j;
        atomicAdd(&g_cnt[j], 1);
    }
}

__global__ void scan1_kernel()   // block sums of SCAN_CH chunks
{
    __shared__ int sh[256];
    int bid = blockIdx.x, tid = threadIdx.x;
    int base = bid * SCAN_CH + tid * 4;
    int s = 0;
    #pragma unroll
    for (int k = 0; k < 4; k++) {
        int idx = base + k;
        if (idx < ZLEN) s += g_cnt[idx];
    }
    sh[tid] = s; __syncthreads();
    for (int off = 128; off > 0; off >>= 1) {
        if (tid < off) sh[tid] += sh[tid + off];
        __syncthreads();
    }
    if (tid == 0) g_part[bid] = sh[0];
}

__global__ void scan2_kernel()   // exclusive scan of partials (1 thread, tiny)
{
    if (threadIdx.x == 0 && blockIdx.x == 0) {
        int acc = 0;
        for (int b = 0; b < SCAN_NBLK; b++) {
            int v = g_part[b];
            g_part[b] = acc;
            acc += v;
        }
        g_rowptr[ZLEN] = acc;   // = E_RECN
    }
}

__global__ void scan3_kernel()   // per-chunk exclusive scan -> rowptr, fill
{
    __shared__ int sh[256];
    int bid = blockIdx.x, tid = threadIdx.x;
    int base = bid * SCAN_CH + tid * 4;
    int c[4], local[4];
    #pragma unroll
    for (int k = 0; k < 4; k++) {
        int idx = base + k;
        c[k] = (idx < ZLEN) ? g_cnt[idx] : 0;
    }
    int s = 0;
    #pragma unroll
    for (int k = 0; k < 4; k++) { local[k] = s; s += c[k]; }
    sh[tid] = s; __syncthreads();
    // Hillis-Steele inclusive scan over 256
    for (int off = 1; off < 256; off <<= 1) {
        int v = (tid >= off) ? sh[tid - off] : 0;
        __syncthreads();
        sh[tid] += v;
        __syncthreads();
    }
    int tpre = sh[tid] - s;          // exclusive prefix of this thread
    int bbase = g_part[bid];
    #pragma unroll
    for (int k = 0; k < 4; k++) {
        int idx = base + k;
        if (idx < ZLEN) {
            int v = bbase + tpre + local[k];
            g_rowptr[idx] = v;
            g_fill[idx]   = v;
        }
    }
}

__global__ void sort_kernel(const int* __restrict__ rec_tgt,
                            const float* __restrict__ w_rec)
{
    int i      = blockIdx.x * blockDim.x + threadIdx.x;
    int stride = gridDim.x * blockDim.x;
    for (int e = i; e < E_RECN; e += stride) {
        int j = g_zidx[e];
        int pos = atomicAdd(&g_fill[j], 1);
        g_edges[pos] = make_int2(rec_tgt[e], __float_as_int(w_rec[e]));
    }
}

// ------------------------------ scatter kernel -------------------------------
// Input edges: quad-per-thread with bitmask early-out.
// Recurrent edges: frontier-driven CSR rows (only spiking sources).
__global__ __launch_bounds__(256)
void scatter_kernel(const int*   __restrict__ in_src,
                    const int*   __restrict__ in_tgt,
                    const float* __restrict__ w_in,
                    int t)
{
    float* tot = reinterpret_cast<float*>(g_total);
    const int  fcnt  = g_fcount[t & 1];
    const int* flist = g_flist[t & 1];
    const int  nwork = IN_QUADS + fcnt;
    const int  stride = gridDim.x * blockDim.x;

    for (int i = blockIdx.x * blockDim.x + threadIdx.x; i < nwork; i += stride) {
        if (i < IN_QUADS) {
            const int e0 = i * 4;
            int4 si = *reinterpret_cast<const int4*>(&in_src[e0]);
            const unsigned char* xm = &g_xmask[t * N_INN];
            unsigned m0 = xm[si.x], m1 = xm[si.y], m2 = xm[si.z], m3 = xm[si.w];
            if ((m0 | m1 | m2 | m3) == 0u) continue;

            int4   tg = *reinterpret_cast<const int4*>  (&in_tgt[e0]);
            float4 ww = *reinterpret_cast<const float4*>(&w_in[e0]);
            unsigned ms[4]  = {m0, m1, m2, m3};
            int      tgs[4] = {tg.x, tg.y, tg.z, tg.w};
            float    wws[4] = {ww.x, ww.y, ww.z, ww.w};
            #pragma unroll
            for (int k = 0; k < 4; k++) {
                unsigned m = ms[k];
                if (!m) continue;
                float w = wws[k];
                int tgt = tgs[k];
                #pragma unroll
                for (int b = 0; b < BB; b++) {
                    if (m & (1u << b)) atomicAdd(&tot[b * RNN + tgt], w);
                }
            }
        } else {
            int p = flist[i - IN_QUADS];
            int j = p & 0xFFFFFF;
            unsigned m = ((unsigned)p) >> 24;
            int r0 = g_rowptr[j];
            int r1 = g_rowptr[j + 1];
            for (int e = r0; e < r1; e++) {
                int2 tw = g_edges[e];
                float w = __int_as_float(tw.y);
                int tgt = tw.x;
                #pragma unroll
                for (int b = 0; b < BB; b++) {
                    if (m & (1u << b)) atomicAdd(&tot[b * RNN + tgt], w);
                }
            }
        }
    }
}

// ------------------------------ update kernel --------------------------------
// One thread per neuron. Also builds next step's frontier (warp-aggregated).
__global__ __launch_bounds__(256)
void update_kernel(const float*  __restrict__ decay,
                   const float*  __restrict__ current_factor,
                   const float*  __restrict__ v_th,
                   const float*  __restrict__ e_l,
                   const float*  __restrict__ v_reset,
                   const float*  __restrict__ t_ref,
                   const float2* __restrict__ asc_amps,
                   const float*  __restrict__ param_g,
                   const float4* __restrict__ syn_decay,
                   const float4* __restrict__ psc_initial,
                   const float4* __restrict__ bkg4,
                   float*        __restrict__ out,
                   int h_read, int h_write, int t)
{
    int n = blockIdx.x * blockDim.x + threadIdx.x;
    bool valid = (n < NN);

    if (blockIdx.x == 0 && threadIdx.x == 0) g_fcount[t & 1] = 0; // consumed buffer

    unsigned nm = 0;
    if (valid) {
        const float  dec  = decay[n];
        const float  cf   = current_factor[n];
        const float  vth  = v_th[n];
        const float  el   = e_l[n];
        const float  vre  = v_reset[n];
        const float  tref = t_ref[n];
        const float2 amps = asc_amps[n];
        const float2 ad   = g_ascd[n];
        const float  g    = param_g[n];
        const float4 sd   = syn_decay[n];
        const float4 pi   = psc_initial[n];
        const float4 bk   = bkg4[n];

        const float gel    = g * el;
        const float invden = 1.0f / (vth - el);
        const float rstamp = vre - vth;

        unsigned pm = g_zmask[h_read * NN + n];

        #pragma unroll
        for (int b = 0; b < BB; b++) {
            int bn = b * NN + n;
            float4 total = g_total[bn];
            float4 pr = g_psc_rise[bn];
            float4 pc = g_psc[bn];
            float  v  = g_v[bn];
            float  r  = g_r[bn];
            float  a1 = g_a1[bn];
            float  a2 = g_a2[bn];
            float  pz = (pm >> b) & 1u ? 1.0f : 0.0f;

            float input_cur = pc.x + pc.y + pc.z + pc.w;
            float c1   = input_cur + a1 + a2 + gel;
            float newv = dec * v + cf * c1 + pz * rstamp;
            float newr = fmaxf(r + pz * tref - 1.0f, 0.0f);
            float na1  = ad.x * a1 + pz * amps.x;
            float na2  = ad.y * a2 + pz * amps.y;

            float4 npc, npr;
            npc.x = pc.x * sd.x + sd.x * pr.x;
            npc.y = pc.y * sd.y + sd.y * pr.y;
            npc.z = pc.z * sd.z + sd.z * pr.z;
            npc.w = pc.w * sd.w + sd.w * pr.w;
            npr.x = sd.x * pr.x + pi.x * total.x;
            npr.y = sd.y * pr.y + pi.y * total.y;
            npr.z = sd.z * pr.z + pi.z * total.z;
            npr.w = sd.w * pr.w + pi.w * total.w;

            float vsc = (newv - vth) * invden;
            float z = (vsc > 0.0f) ? 1.0f : 0.0f;
            if (newr > 0.0f) z = 0.0f;
            nm |= (z != 0.0f ? 1u : 0u) << b;

            g_v[bn]  = newv;
            g_r[bn]  = newr;
            g_a1[bn] = na1;
            g_a2[bn] = na2;
            g_psc_rise[bn] = npr;
            g_psc[bn]      = npc;
            g_total[bn] = bk;

            out[(t * BB + b) * NN + n] = z;
        }
        g_zmask[h_write * NN + n] = (unsigned char)nm;
    }

    // ---- build frontier for next step (h_next = h_write) ----
    const int nb = (t + 1) & 1;
    const int lane = threadIdx.x & 31;
    #pragma unroll
    for (int k = 0; k < DD; k++) {
        unsigned m = 0;
        if (valid) m = (k == h_write) ? nm : (unsigned)g_zmask[k * NN + n];
        unsigned ball = __ballot_sync(0xffffffffu, m != 0u);
        if (ball) {
            int leader = __ffs(ball) - 1;
            int cnt = __popc(ball);
            int base = 0;
            if (lane == leader) base = atomicAdd(&g_fcount[nb], cnt);
            base = __shfl_sync(0xffffffffu, base, leader);
            if (m) {
                int rank = __popc(ball & ((1u << lane) - 1u));
                int d = k - h_write; if (d < 0) d += DD;
                int j = d * NN + n;
                g_flist[nb][base + rank] = (int)((m << 24) | (unsigned)j);
            }
        }
    }
}

// --------------------------------- launcher ----------------------------------
extern "C" void kernel_launch(void* const* d_in, const int* in_sizes, int n_in,
                              void* d_out, int out_size)
{
    const float* x        = (const float*)d_in[0];
    const float* w_rec    = (const float*)d_in[1];
    const int*   rec_src  = (const int*)  d_in[2];
    const int*   rec_tgt  = (const int*)  d_in[3];
    const float* w_in     = (const float*)d_in[4];
    const int*   in_src   = (const int*)  d_in[5];
    const int*   in_tgt   = (const int*)  d_in[6];
    const float* bkg_w    = (const float*)d_in[7];
    const float* decay    = (const float*)d_in[8];
    const float* cf       = (const float*)d_in[9];
    const float* v_th     = (const float*)d_in[10];
    const float* e_l      = (const float*)d_in[11];
    const float* v_reset  = (const float*)d_in[12];
    const float* t_ref    = (const float*)d_in[13];
    const float2* asc_amps = (const float2*)d_in[14];
    const float2* param_k  = (const float2*)d_in[15];
    const float* param_g   = (const float*)d_in[16];
    const float4* syn_decay   = (const float4*)d_in[17];
    const float4* psc_initial = (const float4*)d_in[18];
    const float* v0        = (const float*)d_in[19];
    float* out = (float*)d_out;

    init_kernel<<<1024, 256>>>(x, bkg_w, param_k, v0);

    // one-time CSR build (counting sort by zidx)
    hist_kernel<<<1024, 256>>>(rec_src);
    scan1_kernel<<<SCAN_NBLK, 256>>>();
    scan2_kernel<<<1, 32>>>();
    scan3_kernel<<<SCAN_NBLK, 256>>>();
    sort_kernel<<<1024, 256>>>(rec_tgt, w_rec);

    const int update_blocks = (NN + 255) / 256;

    int h = 0;
    for (int t = 0; t < TT; t++) {
        int h_read  = h;
        int h_write = (h + DD - 1) % DD;
        scatter_kernel<<<512, 256>>>(in_src, in_tgt, w_in, t);
        update_kernel<<<update_blocks, 256>>>(decay, cf, v_th, e_l, v_reset, t_ref,
                                              asc_amps, param_g, syn_decay, psc_initial,
                                              (const float4*)bkg_w, out,
                                              h_read, h_write, t);
        h = h_write;
    }
}